// round 1
// baseline (speedup 1.0000x reference)
#include <cuda_runtime.h>
#include <math.h>

// Problem constants (fixed shapes)
constexpr int B_  = 2;
constexpr int S_  = 2048;
constexpr int D_  = 1024;
constexpr int H_  = 16;
constexpr int DK_ = 64;
constexpr int DF_ = 4096;
constexpr int BS_ = B_ * S_;   // 4096 rows
constexpr int BH_ = B_ * H_;   // 32 (b,h) pairs

// ---------------- scratch (static device globals; no allocs) ----------------
__device__ float g_xa[BS_ * D_];                    // LN1 output
__device__ float g_q[BH_ * S_ * DK_];               // [B*H, S, DK]
__device__ float g_k[BH_ * S_ * DK_];
__device__ float g_v[BH_ * S_ * DK_];
__device__ float g_scores[(long)BH_ * S_ * S_];     // [B*H, S, S]  (~537 MB)
__device__ float g_ctx[BS_ * D_];                   // merged heads [B*S, D]
__device__ float g_x2[BS_ * D_];                    // x + attn_out
__device__ float g_xf[BS_ * D_];                    // LN2 output
__device__ float g_hid[(long)BS_ * DF_];            // FFN hidden (~64 MB)

// ---------------- LayerNorm: one block (256 thr) per row of D=1024 ----------
__global__ void ln_kernel(const float* __restrict__ x, const float* __restrict__ g,
                          const float* __restrict__ b, float* __restrict__ out) {
    constexpr int NCOL = D_ / 256;  // 4
    int row = blockIdx.x;
    const float* xr = x + (size_t)row * D_;
    float v[NCOL];
    float s = 0.f, s2 = 0.f;
#pragma unroll
    for (int i = 0; i < NCOL; i++) {
        float t = xr[threadIdx.x + i * 256];
        v[i] = t; s += t; s2 += t * t;
    }
#pragma unroll
    for (int o = 16; o > 0; o >>= 1) {
        s  += __shfl_xor_sync(0xffffffffu, s, o);
        s2 += __shfl_xor_sync(0xffffffffu, s2, o);
    }
    __shared__ float sh[2][8];
    int warp = threadIdx.x >> 5, lane = threadIdx.x & 31;
    if (lane == 0) { sh[0][warp] = s; sh[1][warp] = s2; }
    __syncthreads();
    if (warp == 0) {
        s  = (lane < 8) ? sh[0][lane] : 0.f;
        s2 = (lane < 8) ? sh[1][lane] : 0.f;
#pragma unroll
        for (int o = 4; o > 0; o >>= 1) {
            s  += __shfl_xor_sync(0xffffffffu, s, o);
            s2 += __shfl_xor_sync(0xffffffffu, s2, o);
        }
        if (lane == 0) { sh[0][0] = s; sh[1][0] = s2; }
    }
    __syncthreads();
    float mu  = sh[0][0] * (1.f / D_);
    float var = sh[1][0] * (1.f / D_) - mu * mu;
    float rstd = rsqrtf(var + 1e-5f);
    float* orow = out + (size_t)row * D_;
#pragma unroll
    for (int i = 0; i < NCOL; i++) {
        int c = threadIdx.x + i * 256;
        orow[c] = (v[i] - mu) * rstd * g[c] + b[c];
    }
}

// ---------------- masked softmax over rows of g_scores ----------------------
// one block (256 thr) per row; rows = BH_*S_; row r -> (b,h,q): b = r/(H*S), q = r%S
__global__ void softmax_kernel(float* __restrict__ sc, const int* __restrict__ mask) {
    constexpr int PER = S_ / 256;  // 8
    int r  = blockIdx.x;
    int b  = r / (H_ * S_);
    int qi = r & (S_ - 1);
    float* sr = sc + (size_t)r * S_;
    const int* mr = mask + ((size_t)b * S_ + qi) * S_;

    float v[PER];
    float mx = -3.0e38f;
#pragma unroll
    for (int i = 0; i < PER; i++) {
        int kk = threadIdx.x + i * 256;
        float t = sr[kk];
        if (mr[kk] == 0) t = -1e9f;
        v[i] = t;
        mx = fmaxf(mx, t);
    }
    // block max
#pragma unroll
    for (int o = 16; o > 0; o >>= 1) mx = fmaxf(mx, __shfl_xor_sync(0xffffffffu, mx, o));
    __shared__ float sh[8];
    int warp = threadIdx.x >> 5, lane = threadIdx.x & 31;
    if (lane == 0) sh[warp] = mx;
    __syncthreads();
    if (warp == 0) {
        mx = (lane < 8) ? sh[lane] : -3.0e38f;
#pragma unroll
        for (int o = 4; o > 0; o >>= 1) mx = fmaxf(mx, __shfl_xor_sync(0xffffffffu, mx, o));
        if (lane == 0) sh[0] = mx;
    }
    __syncthreads();
    mx = sh[0];
    __syncthreads();

    float sum = 0.f;
#pragma unroll
    for (int i = 0; i < PER; i++) { v[i] = expf(v[i] - mx); sum += v[i]; }
#pragma unroll
    for (int o = 16; o > 0; o >>= 1) sum += __shfl_xor_sync(0xffffffffu, sum, o);
    if (lane == 0) sh[warp] = sum;
    __syncthreads();
    if (warp == 0) {
        sum = (lane < 8) ? sh[lane] : 0.f;
#pragma unroll
        for (int o = 4; o > 0; o >>= 1) sum += __shfl_xor_sync(0xffffffffu, sum, o);
        if (lane == 0) sh[0] = sum;
    }
    __syncthreads();
    float inv = 1.f / sh[0];
#pragma unroll
    for (int i = 0; i < PER; i++) {
        int kk = threadIdx.x + i * 256;
        sr[kk] = v[i] * inv;
    }
}

// ---------------- tiled fp32 GEMM, batched, with epilogues ------------------
// C = scale * A(MxK) * op(B) [+bias][+relu][+residual]
// TB: B is [N,K] row-major and used transposed.
// Batch z: base += (z/hdiv)*So + (z%hdiv)*Si  for A, B, C, residual.
// EPI: 0 plain, 1 split-heads (proj -> [B*H,S,DK]), 2 bias+residual, 3 bias+relu
template<int BM, int BN, int BK, int TM, int TN, bool TB, int EPI>
__global__ void __launch_bounds__((BM / TM) * (BN / TN))
gemm_kernel(const float* __restrict__ Ab, const float* __restrict__ Bb, float* __restrict__ Cb,
            int M, int N, int K, int lda, int ldb, int ldc,
            int hdiv, long aSo, long aSi, long bSo, long bSi, long cSo, long cSi,
            const float* __restrict__ bias, const float* __restrict__ res,
            int ldres, long rSo, long rSi, float scale) {
    constexpr int THREADS = (BM / TM) * (BN / TN);
    const int z  = blockIdx.z;
    const int zo = z / hdiv, zi = z % hdiv;
    const float* A  = Ab + zo * aSo + zi * aSi;
    const float* Bp = Bb + zo * bSo + zi * bSi;
    float* C        = Cb + zo * cSo + zi * cSi;

    __shared__ float As[BK][BM];
    __shared__ float Bs[BK][BN];

    const int tid = threadIdx.x;
    const int tx  = tid % (BN / TN);
    const int ty  = tid / (BN / TN);
    const int bm  = blockIdx.y * BM;
    const int bn  = blockIdx.x * BN;

    float acc[TM][TN];
#pragma unroll
    for (int i = 0; i < TM; i++)
#pragma unroll
        for (int j = 0; j < TN; j++) acc[i][j] = 0.f;

    constexpr int A_F4 = BM * BK / 4;
    constexpr int B_F4 = BK * BN / 4;

    for (int k0 = 0; k0 < K; k0 += BK) {
        // A tile: load float4 along K, store transposed
#pragma unroll
        for (int t = tid; t < A_F4; t += THREADS) {
            int row = t / (BK / 4);
            int kq  = (t % (BK / 4)) * 4;
            float4 a = *reinterpret_cast<const float4*>(A + (size_t)(bm + row) * lda + k0 + kq);
            As[kq + 0][row] = a.x; As[kq + 1][row] = a.y;
            As[kq + 2][row] = a.z; As[kq + 3][row] = a.w;
        }
        if (TB) {
#pragma unroll
            for (int t = tid; t < B_F4; t += THREADS) {
                int col = t / (BK / 4);
                int kq  = (t % (BK / 4)) * 4;
                float4 bv = *reinterpret_cast<const float4*>(Bp + (size_t)(bn + col) * ldb + k0 + kq);
                Bs[kq + 0][col] = bv.x; Bs[kq + 1][col] = bv.y;
                Bs[kq + 2][col] = bv.z; Bs[kq + 3][col] = bv.w;
            }
        } else {
#pragma unroll
            for (int t = tid; t < B_F4; t += THREADS) {
                int krow = t / (BN / 4);
                int col  = (t % (BN / 4)) * 4;
                float4 bv = *reinterpret_cast<const float4*>(Bp + (size_t)(k0 + krow) * ldb + bn + col);
                Bs[krow][col + 0] = bv.x; Bs[krow][col + 1] = bv.y;
                Bs[krow][col + 2] = bv.z; Bs[krow][col + 3] = bv.w;
            }
        }
        __syncthreads();
#pragma unroll
        for (int kk = 0; kk < BK; kk++) {
            float ra[TM], rb[TN];
#pragma unroll
            for (int i = 0; i < TM; i++) ra[i] = As[kk][ty * TM + i];
#pragma unroll
            for (int j = 0; j < TN; j++) rb[j] = Bs[kk][tx * TN + j];
#pragma unroll
            for (int i = 0; i < TM; i++)
#pragma unroll
                for (int j = 0; j < TN; j++) acc[i][j] = fmaf(ra[i], rb[j], acc[i][j]);
        }
        __syncthreads();
    }

    const float* R = (EPI == 2) ? (res + zo * rSo + zi * rSi) : nullptr;
#pragma unroll
    for (int i = 0; i < TM; i++) {
        int m = bm + ty * TM + i;
#pragma unroll
        for (int j = 0; j < TN; j++) {
            int n = bn + tx * TN + j;
            float vv = acc[i][j] * scale;
            if (EPI == 0) {
                C[(size_t)m * ldc + n] = vv;
            } else if (EPI == 1) {
                // m = b*S + s ; n = h*DK + dk  -> [(b*H+h)*S + s]*DK + dk
                int bh = (m >> 11) * H_ + (n >> 6);
                C[((size_t)bh * S_ + (m & (S_ - 1))) * DK_ + (n & (DK_ - 1))] = vv;
            } else if (EPI == 2) {
                C[(size_t)m * ldc + n] = vv + bias[n] + R[(size_t)m * ldres + n];
            } else {  // EPI == 3
                C[(size_t)m * ldc + n] = fmaxf(vv + bias[n], 0.f);
            }
        }
    }
}

// ---------------- launch ----------------------------------------------------
extern "C" void kernel_launch(void* const* d_in, const int* in_sizes, int n_in,
                              void* d_out, int out_size) {
    (void)in_sizes; (void)n_in; (void)out_size;
    const float* x   = (const float*)d_in[0];
    const int*   msk = (const int*)d_in[1];
    const float* Wq  = (const float*)d_in[2];
    const float* Wk  = (const float*)d_in[3];
    const float* Wv  = (const float*)d_in[4];
    const float* Wo  = (const float*)d_in[5];
    const float* bo  = (const float*)d_in[6];
    const float* g1  = (const float*)d_in[7];
    const float* be1 = (const float*)d_in[8];
    const float* g2  = (const float*)d_in[9];
    const float* be2 = (const float*)d_in[10];
    const float* W1  = (const float*)d_in[11];
    const float* b1  = (const float*)d_in[12];
    const float* W2  = (const float*)d_in[13];
    const float* b2  = (const float*)d_in[14];
    float* out = (float*)d_out;

    float *xa, *q, *k, *v, *sc, *ctx, *x2, *xf, *hid;
    cudaGetSymbolAddress((void**)&xa,  g_xa);
    cudaGetSymbolAddress((void**)&q,   g_q);
    cudaGetSymbolAddress((void**)&k,   g_k);
    cudaGetSymbolAddress((void**)&v,   g_v);
    cudaGetSymbolAddress((void**)&sc,  g_scores);
    cudaGetSymbolAddress((void**)&ctx, g_ctx);
    cudaGetSymbolAddress((void**)&x2,  g_x2);
    cudaGetSymbolAddress((void**)&xf,  g_xf);
    cudaGetSymbolAddress((void**)&hid, g_hid);

    // 1) LN1
    ln_kernel<<<BS_, 256>>>(x, g1, be1, xa);

    // 2) Q,K,V projections: [4096,1024] @ [1024,1024], split-heads epilogue
    dim3 gProj(D_ / 128, BS_ / 128, 1);
    gemm_kernel<128,128,8,8,8,false,1><<<gProj, 256>>>(
        xa, Wq, q, BS_, D_, D_, D_, D_, 0,
        1, 0,0, 0,0, 0,0, nullptr, nullptr, 0, 0,0, 1.f);
    gemm_kernel<128,128,8,8,8,false,1><<<gProj, 256>>>(
        xa, Wk, k, BS_, D_, D_, D_, D_, 0,
        1, 0,0, 0,0, 0,0, nullptr, nullptr, 0, 0,0, 1.f);
    gemm_kernel<128,128,8,8,8,false,1><<<gProj, 256>>>(
        xa, Wv, v, BS_, D_, D_, D_, D_, 0,
        1, 0,0, 0,0, 0,0, nullptr, nullptr, 0, 0,0, 1.f);

    // 3) scores = (q @ k^T) / 8, batched over 32 (b,h)
    dim3 gScore(S_ / 128, S_ / 128, BH_);
    gemm_kernel<128,128,8,8,8,true,0><<<gScore, 256>>>(
        q, k, sc, S_, S_, DK_, DK_, DK_, S_,
        1, (long)S_ * DK_, 0, (long)S_ * DK_, 0, (long)S_ * S_, 0,
        nullptr, nullptr, 0, 0,0, 0.125f);

    // 4) masked softmax rows
    softmax_kernel<<<BH_ * S_, 256>>>(sc, msk);

    // 5) ctx = probs @ v, batched; write merged-head layout [B*S, D]
    dim3 gCtx(DK_ / 64, S_ / 128, BH_);
    gemm_kernel<128,64,8,8,4,false,0><<<gCtx, 256>>>(
        sc, v, ctx, S_, DK_, S_, S_, DK_, D_,
        H_, (long)H_ * S_ * S_, (long)S_ * S_,
        (long)H_ * S_ * DK_, (long)S_ * DK_,
        (long)S_ * D_, (long)DK_,
        nullptr, nullptr, 0, 0,0, 1.f);

    // 6) x2 = x + ctx @ Wo + bo
    gemm_kernel<128,128,8,8,8,false,2><<<gProj, 256>>>(
        ctx, Wo, x2, BS_, D_, D_, D_, D_, D_,
        1, 0,0, 0,0, 0,0, bo, x, D_, 0,0, 1.f);

    // 7) LN2
    ln_kernel<<<BS_, 256>>>(x2, g2, be2, xf);

    // 8) hid = relu(xf @ W1 + b1)
    dim3 gF1(DF_ / 128, BS_ / 128, 1);
    gemm_kernel<128,128,8,8,8,false,3><<<gF1, 256>>>(
        xf, W1, hid, BS_, DF_, D_, D_, DF_, DF_,
        1, 0,0, 0,0, 0,0, b1, nullptr, 0, 0,0, 1.f);

    // 9) out = x2 + hid @ W2 + b2
    dim3 gF2(D_ / 128, BS_ / 128, 1);
    gemm_kernel<128,128,8,8,8,false,2><<<gF2, 256>>>(
        hid, W2, out, BS_, D_, DF_, DF_, D_, D_,
        1, 0,0, 0,0, 0,0, b2, x2, D_, 0,0, 1.f);
}

// round 2
// speedup vs baseline: 1.6473x; 1.6473x over previous
#include <cuda_runtime.h>
#include <cuda_bf16.h>
#include <math.h>

// Problem constants (fixed shapes)
constexpr int B_  = 2;
constexpr int S_  = 2048;
constexpr int D_  = 1024;
constexpr int H_  = 16;
constexpr int DK_ = 64;
constexpr int DF_ = 4096;
constexpr int BS_ = B_ * S_;   // 4096 rows
constexpr int BH_ = B_ * H_;   // 32 (b,h) pairs

// ---------------- scratch (static device globals; no allocs) ----------------
__device__ float g_xa[BS_ * D_];                    // LN1 output
__device__ float g_q[BH_ * S_ * DK_];               // [B*H, S, DK]
__device__ float g_k[BH_ * S_ * DK_];
__device__ float g_v[BH_ * S_ * DK_];
__device__ float g_scores[(long)BH_ * S_ * S_];     // [B*H, S, S]
__device__ float g_ctx[BS_ * D_];                   // merged heads [B*S, D]
__device__ float g_x2[BS_ * D_];                    // x + attn_out
__device__ float g_xf[BS_ * D_];                    // LN2 output
__device__ float g_hid[(long)BS_ * DF_];            // FFN hidden

// ---------------- helpers ----------------------------------------------------
// hi = exact bf16 truncation (top 16 bits), lo = residual
__device__ __forceinline__ void split2(float x, float& hf, float& lf) {
    unsigned u = __float_as_uint(x) & 0xffff0000u;
    hf = __uint_as_float(u);
    lf = x - hf;
}
// pack two floats into bf16x2 register: low half = eK, high half = eK1
__device__ __forceinline__ unsigned pack_bf2(float eK, float eK1) {
    unsigned r;
    asm("cvt.rn.bf16x2.f32 %0, %1, %2;" : "=r"(r) : "f"(eK1), "f"(eK));
    return r;
}

__device__ __forceinline__ void mma16816(float* c, const unsigned* a, const unsigned* b) {
    asm volatile(
        "mma.sync.aligned.m16n8k16.row.col.f32.bf16.bf16.f32 "
        "{%0,%1,%2,%3},{%4,%5,%6,%7},{%8,%9},{%0,%1,%2,%3};\n"
        : "+f"(c[0]), "+f"(c[1]), "+f"(c[2]), "+f"(c[3])
        : "r"(a[0]), "r"(a[1]), "r"(a[2]), "r"(a[3]), "r"(b[0]), "r"(b[1]));
}

// ---------------- LayerNorm: one block (256 thr) per row of D=1024 ----------
__global__ void ln_kernel(const float* __restrict__ x, const float* __restrict__ g,
                          const float* __restrict__ b, float* __restrict__ out) {
    constexpr int NCOL = D_ / 256;  // 4
    int row = blockIdx.x;
    const float* xr = x + (size_t)row * D_;
    float v[NCOL];
    float s = 0.f, s2 = 0.f;
#pragma unroll
    for (int i = 0; i < NCOL; i++) {
        float t = xr[threadIdx.x + i * 256];
        v[i] = t; s += t; s2 += t * t;
    }
#pragma unroll
    for (int o = 16; o > 0; o >>= 1) {
        s  += __shfl_xor_sync(0xffffffffu, s, o);
        s2 += __shfl_xor_sync(0xffffffffu, s2, o);
    }
    __shared__ float sh[2][8];
    int warp = threadIdx.x >> 5, lane = threadIdx.x & 31;
    if (lane == 0) { sh[0][warp] = s; sh[1][warp] = s2; }
    __syncthreads();
    if (warp == 0) {
        s  = (lane < 8) ? sh[0][lane] : 0.f;
        s2 = (lane < 8) ? sh[1][lane] : 0.f;
#pragma unroll
        for (int o = 4; o > 0; o >>= 1) {
            s  += __shfl_xor_sync(0xffffffffu, s, o);
            s2 += __shfl_xor_sync(0xffffffffu, s2, o);
        }
        if (lane == 0) { sh[0][0] = s; sh[1][0] = s2; }
    }
    __syncthreads();
    float mu  = sh[0][0] * (1.f / D_);
    float var = sh[1][0] * (1.f / D_) - mu * mu;
    float rstd = rsqrtf(var + 1e-5f);
    float* orow = out + (size_t)row * D_;
#pragma unroll
    for (int i = 0; i < NCOL; i++) {
        int c = threadIdx.x + i * 256;
        orow[c] = (v[i] - mu) * rstd * g[c] + b[c];
    }
}

// ---------------- masked softmax over rows of g_scores ----------------------
__global__ void softmax_kernel(float* __restrict__ sc, const int* __restrict__ mask) {
    constexpr int PER = S_ / 256;  // 8
    int r  = blockIdx.x;
    int b  = r / (H_ * S_);
    int qi = r & (S_ - 1);
    float* sr = sc + (size_t)r * S_;
    const int* mr = mask + ((size_t)b * S_ + qi) * S_;

    float v[PER];
    float mx = -3.0e38f;
#pragma unroll
    for (int i = 0; i < PER; i++) {
        int kk = threadIdx.x + i * 256;
        float t = sr[kk];
        if (mr[kk] == 0) t = -1e9f;
        v[i] = t;
        mx = fmaxf(mx, t);
    }
#pragma unroll
    for (int o = 16; o > 0; o >>= 1) mx = fmaxf(mx, __shfl_xor_sync(0xffffffffu, mx, o));
    __shared__ float sh[8];
    int warp = threadIdx.x >> 5, lane = threadIdx.x & 31;
    if (lane == 0) sh[warp] = mx;
    __syncthreads();
    if (warp == 0) {
        mx = (lane < 8) ? sh[lane] : -3.0e38f;
#pragma unroll
        for (int o = 4; o > 0; o >>= 1) mx = fmaxf(mx, __shfl_xor_sync(0xffffffffu, mx, o));
        if (lane == 0) sh[0] = mx;
    }
    __syncthreads();
    mx = sh[0];
    __syncthreads();

    float sum = 0.f;
#pragma unroll
    for (int i = 0; i < PER; i++) { v[i] = expf(v[i] - mx); sum += v[i]; }
#pragma unroll
    for (int o = 16; o > 0; o >>= 1) sum += __shfl_xor_sync(0xffffffffu, sum, o);
    if (lane == 0) sh[warp] = sum;
    __syncthreads();
    if (warp == 0) {
        sum = (lane < 8) ? sh[lane] : 0.f;
#pragma unroll
        for (int o = 4; o > 0; o >>= 1) sum += __shfl_xor_sync(0xffffffffu, sum, o);
        if (lane == 0) sh[0] = sum;
    }
    __syncthreads();
    float inv = 1.f / sh[0];
#pragma unroll
    for (int i = 0; i < PER; i++) {
        int kk = threadIdx.x + i * 256;
        sr[kk] = v[i] * inv;
    }
}

// ---------------- bf16-split tensor-core GEMM --------------------------------
// C = scale * A(MxK) * op(B) [+bias][+relu][+residual], fp32 in/out.
// Each fp32 operand is split hi/lo (bf16); acc += Ahi*Bhi + Ahi*Blo + Alo*Bhi.
// TB: B is [N,K] row-major used transposed. Batch z offsets as before.
// EPI: 0 plain, 1 split-heads, 2 bias+residual, 3 bias+relu
template<int BM, int BN, int WARPS_M, int WARPS_N, bool TB, int EPI>
__global__ void __launch_bounds__(WARPS_M * WARPS_N * 32, 1)
gemm_mma(const float* __restrict__ Ab, const float* __restrict__ Bb, float* __restrict__ Cb,
         int K, int lda, int ldb, int ldc,
         int hdiv, long aSo, long aSi, long bSo, long bSi, long cSo, long cSi,
         const float* __restrict__ bias, const float* __restrict__ res,
         int ldres, float scale) {
    constexpr int THREADS = WARPS_M * WARPS_N * 32;
    constexpr int BK = 32;
    constexpr int KW = BK / 2 + 2;       // padded k-pair words per row (18)
    constexpr int WM = BM / WARPS_M;
    constexpr int WN = BN / WARPS_N;
    constexpr int MT = WM / 16;
    constexpr int NT = WN / 8;

    const int z  = blockIdx.z;
    const int zo = z / hdiv, zi = z % hdiv;
    const float* A  = Ab + zo * aSo + zi * aSi;
    const float* Bp = Bb + zo * bSo + zi * bSi;
    float* C        = Cb + zo * cSo + zi * cSi;

    __shared__ unsigned As[2][BM][KW];
    __shared__ unsigned Bs[2][BN][KW];

    const int tid  = threadIdx.x;
    const int warp = tid >> 5, lane = tid & 31;
    const int wm   = warp / WARPS_N, wn = warp % WARPS_N;
    const int bm   = blockIdx.y * BM;
    const int bn   = blockIdx.x * BN;

    float acc[MT][NT][4];
#pragma unroll
    for (int i = 0; i < MT; i++)
#pragma unroll
        for (int j = 0; j < NT; j++)
#pragma unroll
            for (int r = 0; r < 4; r++) acc[i][j][r] = 0.f;

    for (int k0 = 0; k0 < K; k0 += BK) {
        // ---- A tile: fp32 float4 -> hi/lo bf16 pairs  (BM x BK) ----
        constexpr int A_ITERS = BM * (BK / 4) / THREADS;  // 4
#pragma unroll
        for (int i = 0; i < A_ITERS; i++) {
            int idx = tid + i * THREADS;
            int row = idx >> 3;           // /(BK/4)
            int q   = idx & 7;
            float4 a = *reinterpret_cast<const float4*>(A + (size_t)(bm + row) * lda + k0 + q * 4);
            float hx, lx, hy, ly, hz, lz, hw, lw;
            split2(a.x, hx, lx); split2(a.y, hy, ly);
            split2(a.z, hz, lz); split2(a.w, hw, lw);
            As[0][row][q * 2 + 0] = pack_bf2(hx, hy);
            As[0][row][q * 2 + 1] = pack_bf2(hz, hw);
            As[1][row][q * 2 + 0] = pack_bf2(lx, ly);
            As[1][row][q * 2 + 1] = pack_bf2(lz, lw);
        }
        // ---- B tile -> Bs[n][kpair] ----
        if (TB) {
            constexpr int B_ITERS = BN * (BK / 4) / THREADS;
#pragma unroll
            for (int i = 0; i < B_ITERS; i++) {
                int idx = tid + i * THREADS;
                int n = idx >> 3;
                int q = idx & 7;
                float4 bv = *reinterpret_cast<const float4*>(Bp + (size_t)(bn + n) * ldb + k0 + q * 4);
                float hx, lx, hy, ly, hz, lz, hw, lw;
                split2(bv.x, hx, lx); split2(bv.y, hy, ly);
                split2(bv.z, hz, lz); split2(bv.w, hw, lw);
                Bs[0][n][q * 2 + 0] = pack_bf2(hx, hy);
                Bs[0][n][q * 2 + 1] = pack_bf2(hz, hw);
                Bs[1][n][q * 2 + 0] = pack_bf2(lx, ly);
                Bs[1][n][q * 2 + 1] = pack_bf2(lz, lw);
            }
        } else {
            constexpr int B_ITERS = (BK / 2) * (BN / 4) / THREADS;  // 2 or 1
#pragma unroll
            for (int i = 0; i < B_ITERS; i++) {
                int idx = tid + i * THREADS;
                int kp  = idx / (BN / 4);       // k-pair index 0..15
                int nq  = idx % (BN / 4);
                int n0  = nq * 4;
                const float* r0 = Bp + (size_t)(k0 + kp * 2) * ldb + bn + n0;
                float4 b0 = *reinterpret_cast<const float4*>(r0);
                float4 b1 = *reinterpret_cast<const float4*>(r0 + ldb);
                float h0, l0, h1, l1;
#pragma unroll
                for (int j = 0; j < 4; j++) {
                    float e0 = (j == 0) ? b0.x : (j == 1) ? b0.y : (j == 2) ? b0.z : b0.w;
                    float e1 = (j == 0) ? b1.x : (j == 1) ? b1.y : (j == 2) ? b1.z : b1.w;
                    split2(e0, h0, l0); split2(e1, h1, l1);
                    Bs[0][n0 + j][kp] = pack_bf2(h0, h1);
                    Bs[1][n0 + j][kp] = pack_bf2(l0, l1);
                }
            }
        }
        __syncthreads();

        // ---- two k16 steps of MMA ----
#pragma unroll
        for (int s = 0; s < 2; s++) {
            unsigned af[2][MT][4];
            unsigned bf[2][NT][2];
            int c0 = s * 8 + (lane & 3);
#pragma unroll
            for (int h = 0; h < 2; h++) {
#pragma unroll
                for (int mt = 0; mt < MT; mt++) {
                    int r0 = wm * WM + mt * 16 + (lane >> 2);
                    af[h][mt][0] = As[h][r0][c0];
                    af[h][mt][1] = As[h][r0 + 8][c0];
                    af[h][mt][2] = As[h][r0][c0 + 4];
                    af[h][mt][3] = As[h][r0 + 8][c0 + 4];
                }
#pragma unroll
                for (int nt = 0; nt < NT; nt++) {
                    int n = wn * WN + nt * 8 + (lane >> 2);
                    bf[h][nt][0] = Bs[h][n][c0];
                    bf[h][nt][1] = Bs[h][n][c0 + 4];
                }
            }
#pragma unroll
            for (int mt = 0; mt < MT; mt++)
#pragma unroll
                for (int nt = 0; nt < NT; nt++) {
                    mma16816(acc[mt][nt], af[0][mt], bf[1][nt]);  // hi*lo
                    mma16816(acc[mt][nt], af[1][mt], bf[0][nt]);  // lo*hi
                    mma16816(acc[mt][nt], af[0][mt], bf[0][nt]);  // hi*hi
                }
        }
        __syncthreads();
    }

    // ---- epilogue ----
#pragma unroll
    for (int mt = 0; mt < MT; mt++) {
#pragma unroll
        for (int half = 0; half < 2; half++) {
            int m = bm + wm * WM + mt * 16 + (lane >> 2) + half * 8;
#pragma unroll
            for (int nt = 0; nt < NT; nt++) {
                int n = bn + wn * WN + nt * 8 + (lane & 3) * 2;
                float v0 = acc[mt][nt][half * 2 + 0] * scale;
                float v1 = acc[mt][nt][half * 2 + 1] * scale;
                if (EPI == 0) {
                    C[(size_t)m * ldc + n]     = v0;
                    C[(size_t)m * ldc + n + 1] = v1;
                } else if (EPI == 1) {
                    // m = b*S+s ; n = h*DK+dk -> [(b*H+h)*S+s]*DK+dk
                    int bh = (m >> 11) * H_ + (n >> 6);
                    size_t base = ((size_t)bh * S_ + (m & (S_ - 1))) * DK_ + (n & (DK_ - 1));
                    C[base]     = v0;
                    C[base + 1] = v1;
                } else if (EPI == 2) {
                    C[(size_t)m * ldc + n]     = v0 + bias[n]     + res[(size_t)m * ldres + n];
                    C[(size_t)m * ldc + n + 1] = v1 + bias[n + 1] + res[(size_t)m * ldres + n + 1];
                } else {  // 3: bias + relu
                    C[(size_t)m * ldc + n]     = fmaxf(v0 + bias[n], 0.f);
                    C[(size_t)m * ldc + n + 1] = fmaxf(v1 + bias[n + 1], 0.f);
                }
            }
        }
    }
}

// ---------------- launch ----------------------------------------------------
extern "C" void kernel_launch(void* const* d_in, const int* in_sizes, int n_in,
                              void* d_out, int out_size) {
    (void)in_sizes; (void)n_in; (void)out_size;
    const float* x   = (const float*)d_in[0];
    const int*   msk = (const int*)d_in[1];
    const float* Wq  = (const float*)d_in[2];
    const float* Wk  = (const float*)d_in[3];
    const float* Wv  = (const float*)d_in[4];
    const float* Wo  = (const float*)d_in[5];
    const float* bo  = (const float*)d_in[6];
    const float* g1  = (const float*)d_in[7];
    const float* be1 = (const float*)d_in[8];
    const float* g2  = (const float*)d_in[9];
    const float* be2 = (const float*)d_in[10];
    const float* W1  = (const float*)d_in[11];
    const float* b1  = (const float*)d_in[12];
    const float* W2  = (const float*)d_in[13];
    const float* b2  = (const float*)d_in[14];
    float* out = (float*)d_out;

    float *xa, *q, *k, *v, *sc, *ctx, *x2, *xf, *hid;
    cudaGetSymbolAddress((void**)&xa,  g_xa);
    cudaGetSymbolAddress((void**)&q,   g_q);
    cudaGetSymbolAddress((void**)&k,   g_k);
    cudaGetSymbolAddress((void**)&v,   g_v);
    cudaGetSymbolAddress((void**)&sc,  g_scores);
    cudaGetSymbolAddress((void**)&ctx, g_ctx);
    cudaGetSymbolAddress((void**)&x2,  g_x2);
    cudaGetSymbolAddress((void**)&xf,  g_xf);
    cudaGetSymbolAddress((void**)&hid, g_hid);

    // 1) LN1
    ln_kernel<<<BS_, 256>>>(x, g1, be1, xa);

    // 2) Q,K,V projections with split-heads epilogue
    dim3 gProj(D_ / 128, BS_ / 128, 1);
    gemm_mma<128,128,2,4,false,1><<<gProj, 256>>>(
        xa, Wq, q, D_, D_, D_, 0,
        1, 0,0, 0,0, 0,0, nullptr, nullptr, 0, 1.f);
    gemm_mma<128,128,2,4,false,1><<<gProj, 256>>>(
        xa, Wk, k, D_, D_, D_, 0,
        1, 0,0, 0,0, 0,0, nullptr, nullptr, 0, 1.f);
    gemm_mma<128,128,2,4,false,1><<<gProj, 256>>>(
        xa, Wv, v, D_, D_, D_, 0,
        1, 0,0, 0,0, 0,0, nullptr, nullptr, 0, 1.f);

    // 3) scores = (q @ k^T) / 8, batched over 32 (b,h)
    dim3 gScore(S_ / 128, S_ / 128, BH_);
    gemm_mma<128,128,2,4,true,0><<<gScore, 256>>>(
        q, k, sc, DK_, DK_, DK_, S_,
        1, (long)S_ * DK_, 0, (long)S_ * DK_, 0, (long)S_ * S_, 0,
        nullptr, nullptr, 0, 0.125f);

    // 4) masked softmax
    softmax_kernel<<<BH_ * S_, 256>>>(sc, msk);

    // 5) ctx = probs @ v  (BN=64), merged-head output layout
    dim3 gCtx(1, S_ / 128, BH_);
    gemm_mma<128,64,4,2,false,0><<<gCtx, 256>>>(
        sc, v, ctx, S_, S_, DK_, D_,
        H_, (long)H_ * S_ * S_, (long)S_ * S_,
        (long)H_ * S_ * DK_, (long)S_ * DK_,
        (long)S_ * D_, (long)DK_,
        nullptr, nullptr, 0, 1.f);

    // 6) x2 = x + ctx @ Wo + bo
    gemm_mma<128,128,2,4,false,2><<<gProj, 256>>>(
        ctx, Wo, x2, D_, D_, D_, D_,
        1, 0,0, 0,0, 0,0, bo, x, D_, 1.f);

    // 7) LN2
    ln_kernel<<<BS_, 256>>>(x2, g2, be2, xf);

    // 8) hid = relu(xf @ W1 + b1)
    dim3 gF1(DF_ / 128, BS_ / 128, 1);
    gemm_mma<128,128,2,4,false,3><<<gF1, 256>>>(
        xf, W1, hid, D_, D_, DF_, DF_,
        1, 0,0, 0,0, 0,0, b1, nullptr, 0, 1.f);

    // 9) out = x2 + hid @ W2 + b2
    dim3 gF2(D_ / 128, BS_ / 128, 1);
    gemm_mma<128,128,2,4,false,2><<<gF2, 256>>>(
        hid, W2, out, DF_, DF_, D_, D_,
        1, 0,0, 0,0, 0,0, b2, x2, D_, 1.f);
}

// round 3
// speedup vs baseline: 3.2356x; 1.9641x over previous
#include <cuda_runtime.h>
#include <cuda_bf16.h>
#include <math.h>

constexpr int B_  = 2;
constexpr int S_  = 2048;
constexpr int D_  = 1024;
constexpr int H_  = 16;
constexpr int DK_ = 64;
constexpr int DF_ = 4096;
constexpr int BS_ = B_ * S_;
constexpr int BH_ = B_ * H_;

// ---------------- scratch (static device globals; no allocs) ----------------
__device__ float g_xa[BS_ * D_];
__device__ float g_q[BH_ * S_ * DK_];
__device__ float g_k[BH_ * S_ * DK_];
__device__ float g_v[BH_ * S_ * DK_];
__device__ float g_ctx[BS_ * D_];
__device__ float g_x2[BS_ * D_];
__device__ float g_xf[BS_ * D_];
__device__ float g_hid[(long)BS_ * DF_];

// ---------------- helpers ----------------------------------------------------
__device__ __forceinline__ void split2(float x, float& hf, float& lf) {
    unsigned u = __float_as_uint(x) & 0xffff0000u;
    hf = __uint_as_float(u);
    lf = x - hf;
}
__device__ __forceinline__ unsigned pack_bf2(float eK, float eK1) {
    unsigned r;
    asm("cvt.rn.bf16x2.f32 %0, %1, %2;" : "=r"(r) : "f"(eK1), "f"(eK));
    return r;
}
__device__ __forceinline__ void mma16816(float* c, const unsigned* a, const unsigned* b) {
    asm volatile(
        "mma.sync.aligned.m16n8k16.row.col.f32.bf16.bf16.f32 "
        "{%0,%1,%2,%3},{%4,%5,%6,%7},{%8,%9},{%0,%1,%2,%3};\n"
        : "+f"(c[0]), "+f"(c[1]), "+f"(c[2]), "+f"(c[3])
        : "r"(a[0]), "r"(a[1]), "r"(a[2]), "r"(a[3]), "r"(b[0]), "r"(b[1]));
}

// ---------------- LayerNorm ---------------------------------------------------
__global__ void ln_kernel(const float* __restrict__ x, const float* __restrict__ g,
                          const float* __restrict__ b, float* __restrict__ out) {
    constexpr int NCOL = D_ / 256;
    int row = blockIdx.x;
    const float* xr = x + (size_t)row * D_;
    float v[NCOL];
    float s = 0.f, s2 = 0.f;
#pragma unroll
    for (int i = 0; i < NCOL; i++) {
        float t = xr[threadIdx.x + i * 256];
        v[i] = t; s += t; s2 += t * t;
    }
#pragma unroll
    for (int o = 16; o > 0; o >>= 1) {
        s  += __shfl_xor_sync(0xffffffffu, s, o);
        s2 += __shfl_xor_sync(0xffffffffu, s2, o);
    }
    __shared__ float sh[2][8];
    int warp = threadIdx.x >> 5, lane = threadIdx.x & 31;
    if (lane == 0) { sh[0][warp] = s; sh[1][warp] = s2; }
    __syncthreads();
    if (warp == 0) {
        s  = (lane < 8) ? sh[0][lane] : 0.f;
        s2 = (lane < 8) ? sh[1][lane] : 0.f;
#pragma unroll
        for (int o = 4; o > 0; o >>= 1) {
            s  += __shfl_xor_sync(0xffffffffu, s, o);
            s2 += __shfl_xor_sync(0xffffffffu, s2, o);
        }
        if (lane == 0) { sh[0][0] = s; sh[1][0] = s2; }
    }
    __syncthreads();
    float mu  = sh[0][0] * (1.f / D_);
    float var = sh[1][0] * (1.f / D_) - mu * mu;
    float rstd = rsqrtf(var + 1e-5f);
    float* orow = out + (size_t)row * D_;
#pragma unroll
    for (int i = 0; i < NCOL; i++) {
        int c = threadIdx.x + i * 256;
        orow[c] = (v[i] - mu) * rstd * g[c] + b[c];
    }
}

// ---------------- pipelined bf16-split tensor-core GEMM ----------------------
// C = A(MxK fp32) * B(KxN fp32) [+bias][+relu][+residual]
// 2-stage SMEM ping-pong with register prefetch of next tile.
// EPI: 1 split-heads, 2 bias+residual, 3 bias+relu
template<int EPI>
__global__ void __launch_bounds__(256, 1)
gemm_mma(const float* __restrict__ A, const float* __restrict__ Bp, float* __restrict__ C,
         int K, int lda, int ldb, int ldc,
         const float* __restrict__ bias, const float* __restrict__ res, int ldres) {
    constexpr int BM = 128, BN = 128, BK = 32;
    constexpr int KWA = 20;              // A smem row pitch (u32 words), conflict-free frags
    constexpr int KWB = 136;             // B smem: [h][kp(16)][n(128)+pad]
    constexpr int AW  = 2 * BM * KWA;    // 5120 words per stage (hi+lo)
    constexpr int BW  = 2 * 16 * KWB;    // 4352 words per stage
    constexpr int SS  = AW + BW;         // 9472 words per stage
    extern __shared__ unsigned sm[];

    const int tid = threadIdx.x, warp = tid >> 5, lane = tid & 31;
    const int wm = warp >> 2, wn = warp & 3;           // 2x4 warps
    const int bm = blockIdx.y * BM, bn = blockIdx.x * BN;
    constexpr int MT = 4, NT = 4;                      // warp tile 64x32

    float acc[MT][NT][4] = {};
    float4 ra[4], rb0[2], rb1[2];

    const int arow = tid >> 3, aq = tid & 7;

    auto loadAB = [&](int k0) {
#pragma unroll
        for (int i = 0; i < 4; i++)
            ra[i] = *reinterpret_cast<const float4*>(
                A + (size_t)(bm + arow + i * 32) * lda + k0 + aq * 4);
#pragma unroll
        for (int i = 0; i < 2; i++) {
            int kp = warp + i * 8;
            const float* p0 = Bp + (size_t)(k0 + 2 * kp) * ldb + bn + lane * 4;
            rb0[i] = *reinterpret_cast<const float4*>(p0);
            rb1[i] = *reinterpret_cast<const float4*>(p0 + ldb);
        }
    };
    auto stage_store = [&](int st) {
        unsigned* base = sm + st * SS;
#pragma unroll
        for (int i = 0; i < 4; i++) {
            int row = arow + i * 32;
            float h0, l0, h1, l1, h2, l2, h3, l3;
            split2(ra[i].x, h0, l0); split2(ra[i].y, h1, l1);
            split2(ra[i].z, h2, l2); split2(ra[i].w, h3, l3);
            uint2 hv = make_uint2(pack_bf2(h0, h1), pack_bf2(h2, h3));
            uint2 lv = make_uint2(pack_bf2(l0, l1), pack_bf2(l2, l3));
            *reinterpret_cast<uint2*>(base + row * KWA + aq * 2) = hv;
            *reinterpret_cast<uint2*>(base + BM * KWA + row * KWA + aq * 2) = lv;
        }
        unsigned* bb = base + AW;
#pragma unroll
        for (int i = 0; i < 2; i++) {
            int kp = warp + i * 8;
            float h0, l0, h1, l1;
            uint4 hv, lv;
            split2(rb0[i].x, h0, l0); split2(rb1[i].x, h1, l1);
            hv.x = pack_bf2(h0, h1); lv.x = pack_bf2(l0, l1);
            split2(rb0[i].y, h0, l0); split2(rb1[i].y, h1, l1);
            hv.y = pack_bf2(h0, h1); lv.y = pack_bf2(l0, l1);
            split2(rb0[i].z, h0, l0); split2(rb1[i].z, h1, l1);
            hv.z = pack_bf2(h0, h1); lv.z = pack_bf2(l0, l1);
            split2(rb0[i].w, h0, l0); split2(rb1[i].w, h1, l1);
            hv.w = pack_bf2(h0, h1); lv.w = pack_bf2(l0, l1);
            *reinterpret_cast<uint4*>(bb + kp * KWB + lane * 4) = hv;
            *reinterpret_cast<uint4*>(bb + 16 * KWB + kp * KWB + lane * 4) = lv;
        }
    };
    auto do_mma = [&](int st) {
        const unsigned* Ah = sm + st * SS;
        const unsigned* Al = Ah + BM * KWA;
        const unsigned* Bh = Ah + AW;
        const unsigned* Bl = Bh + 16 * KWB;
#pragma unroll
        for (int s = 0; s < 2; s++) {
            int c0 = s * 8 + (lane & 3);
            unsigned afh[MT][4], afl[MT][4], bfh[NT][2], bfl[NT][2];
#pragma unroll
            for (int mt = 0; mt < MT; mt++) {
                int r0 = wm * 64 + mt * 16 + (lane >> 2);
                afh[mt][0] = Ah[r0 * KWA + c0];       afh[mt][1] = Ah[(r0 + 8) * KWA + c0];
                afh[mt][2] = Ah[r0 * KWA + c0 + 4];   afh[mt][3] = Ah[(r0 + 8) * KWA + c0 + 4];
                afl[mt][0] = Al[r0 * KWA + c0];       afl[mt][1] = Al[(r0 + 8) * KWA + c0];
                afl[mt][2] = Al[r0 * KWA + c0 + 4];   afl[mt][3] = Al[(r0 + 8) * KWA + c0 + 4];
            }
#pragma unroll
            for (int nt = 0; nt < NT; nt++) {
                int n = wn * 32 + nt * 8 + (lane >> 2);
                bfh[nt][0] = Bh[c0 * KWB + n]; bfh[nt][1] = Bh[(c0 + 4) * KWB + n];
                bfl[nt][0] = Bl[c0 * KWB + n]; bfl[nt][1] = Bl[(c0 + 4) * KWB + n];
            }
#pragma unroll
            for (int mt = 0; mt < MT; mt++)
#pragma unroll
                for (int nt = 0; nt < NT; nt++) {
                    mma16816(acc[mt][nt], afh[mt], bfl[nt]);
                    mma16816(acc[mt][nt], afl[mt], bfh[nt]);
                    mma16816(acc[mt][nt], afh[mt], bfh[nt]);
                }
        }
    };

    const int nk = K / BK;
    loadAB(0);
    stage_store(0);
    __syncthreads();
    for (int i = 0; i < nk; i++) {
        if (i + 1 < nk) loadAB((i + 1) * BK);
        do_mma(i & 1);
        if (i + 1 < nk) stage_store((i + 1) & 1);
        __syncthreads();
    }

#pragma unroll
    for (int mt = 0; mt < MT; mt++) {
#pragma unroll
        for (int half = 0; half < 2; half++) {
            int m = bm + wm * 64 + mt * 16 + (lane >> 2) + half * 8;
#pragma unroll
            for (int nt = 0; nt < NT; nt++) {
                int n = bn + wn * 32 + nt * 8 + (lane & 3) * 2;
                float v0 = acc[mt][nt][half * 2 + 0];
                float v1 = acc[mt][nt][half * 2 + 1];
                if (EPI == 1) {
                    int bh = (m >> 11) * H_ + (n >> 6);
                    size_t base = ((size_t)bh * S_ + (m & (S_ - 1))) * DK_ + (n & (DK_ - 1));
                    C[base]     = v0;
                    C[base + 1] = v1;
                } else if (EPI == 2) {
                    C[(size_t)m * ldc + n]     = v0 + bias[n]     + res[(size_t)m * ldres + n];
                    C[(size_t)m * ldc + n + 1] = v1 + bias[n + 1] + res[(size_t)m * ldres + n + 1];
                } else {
                    C[(size_t)m * ldc + n]     = fmaxf(v0 + bias[n], 0.f);
                    C[(size_t)m * ldc + n + 1] = fmaxf(v1 + bias[n + 1], 0.f);
                }
            }
        }
    }
}

// ---------------- fused flash attention --------------------------------------
// grid (1, S/128, B*H); block 256 (8 warps x 16 q-rows each).
// Q,K hi/lo bf16 (3-product scores); P,V plain bf16 (1-product PV).
constexpr int QW = 36;   // [row][dkpair] pitch
constexpr int VW = 72;   // [kvpair][dk] pitch
__global__ void __launch_bounds__(256, 1)
flash_kernel(const float* __restrict__ q, const float* __restrict__ k,
             const float* __restrict__ v, const int* __restrict__ mask,
             float* __restrict__ ctx) {
    extern __shared__ unsigned sm[];
    unsigned* Qs = sm;                       // hi [128][36], lo follows
    unsigned* Ks = sm + 2 * 128 * QW;
    unsigned* Vs = sm + 4 * 128 * QW;        // [64][72]
    const int tid = threadIdx.x, warp = tid >> 5, lane = tid & 31;
    const int bh = blockIdx.z, qt = blockIdx.y;
    const int b = bh >> 4, h = bh & 15;
    const float* Qp = q + ((size_t)bh * S_ + qt * 128) * DK_;
    const float* Kp = k + (size_t)bh * S_ * DK_;
    const float* Vp = v + (size_t)bh * S_ * DK_;
    const int*   Mp = mask + ((size_t)b * S_ + qt * 128) * (size_t)S_;

    // Q tile (pre-scaled by 1/8), split hi/lo
#pragma unroll
    for (int i = 0; i < 8; i++) {
        int idx = tid + i * 256;
        int row = idx >> 4, q4 = idx & 15;
        float4 a = *reinterpret_cast<const float4*>(Qp + row * 64 + q4 * 4);
        a.x *= 0.125f; a.y *= 0.125f; a.z *= 0.125f; a.w *= 0.125f;
        float h0, l0, h1, l1, h2, l2, h3, l3;
        split2(a.x, h0, l0); split2(a.y, h1, l1);
        split2(a.z, h2, l2); split2(a.w, h3, l3);
        *reinterpret_cast<uint2*>(Qs + row * QW + q4 * 2) =
            make_uint2(pack_bf2(h0, h1), pack_bf2(h2, h3));
        *reinterpret_cast<uint2*>(Qs + 128 * QW + row * QW + q4 * 2) =
            make_uint2(pack_bf2(l0, l1), pack_bf2(l2, l3));
    }

    float accc[8][4] = {};
    float m0 = -3.0e38f, m1 = -3.0e38f, l0s = 0.f, l1s = 0.f;
    const int c2 = (lane & 3) * 2;
    const int* mrow0 = Mp + ((size_t)(warp * 16 + (lane >> 2))) * S_;
    const int* mrow1 = mrow0 + 8 * (size_t)S_;

    for (int kt = 0; kt < S_ / 128; kt++) {
        __syncthreads();   // everyone done with previous K/V tiles
        // K tile: split hi/lo
#pragma unroll
        for (int i = 0; i < 8; i++) {
            int idx = tid + i * 256;
            int row = idx >> 4, q4 = idx & 15;
            float4 a = *reinterpret_cast<const float4*>(
                Kp + (size_t)(kt * 128 + row) * 64 + q4 * 4);
            float h0, l0, h1, l1, h2, l2, h3, l3;
            split2(a.x, h0, l0); split2(a.y, h1, l1);
            split2(a.z, h2, l2); split2(a.w, h3, l3);
            *reinterpret_cast<uint2*>(Ks + row * QW + q4 * 2) =
                make_uint2(pack_bf2(h0, h1), pack_bf2(h2, h3));
            *reinterpret_cast<uint2*>(Ks + 128 * QW + row * QW + q4 * 2) =
                make_uint2(pack_bf2(l0, l1), pack_bf2(l2, l3));
        }
        // V tile: plain bf16, packed by kv-pairs
#pragma unroll
        for (int i = 0; i < 4; i++) {
            int idx = tid + i * 256;
            int dk4 = idx & 15, kp = idx >> 4;
            const float* p0 = Vp + (size_t)(kt * 128 + 2 * kp) * 64 + dk4 * 4;
            float4 v0 = *reinterpret_cast<const float4*>(p0);
            float4 v1 = *reinterpret_cast<const float4*>(p0 + 64);
            uint4 pv;
            pv.x = pack_bf2(v0.x, v1.x); pv.y = pack_bf2(v0.y, v1.y);
            pv.z = pack_bf2(v0.z, v1.z); pv.w = pack_bf2(v0.w, v1.w);
            *reinterpret_cast<uint4*>(Vs + kp * VW + dk4 * 4) = pv;
        }
        __syncthreads();

        // S = Q K^T (scaled): accs[16][4]
        float accs[16][4] = {};
#pragma unroll
        for (int s = 0; s < 4; s++) {
            int c0 = s * 8 + (lane & 3);
            int r0 = warp * 16 + (lane >> 2);
            unsigned ah[4], al[4];
            ah[0] = Qs[r0 * QW + c0];       ah[1] = Qs[(r0 + 8) * QW + c0];
            ah[2] = Qs[r0 * QW + c0 + 4];   ah[3] = Qs[(r0 + 8) * QW + c0 + 4];
            al[0] = Qs[128 * QW + r0 * QW + c0];     al[1] = Qs[128 * QW + (r0 + 8) * QW + c0];
            al[2] = Qs[128 * QW + r0 * QW + c0 + 4]; al[3] = Qs[128 * QW + (r0 + 8) * QW + c0 + 4];
#pragma unroll
            for (int nt = 0; nt < 16; nt++) {
                int n = nt * 8 + (lane >> 2);
                unsigned bh2[2], bl2[2];
                bh2[0] = Ks[n * QW + c0];            bh2[1] = Ks[n * QW + c0 + 4];
                bl2[0] = Ks[128 * QW + n * QW + c0]; bl2[1] = Ks[128 * QW + n * QW + c0 + 4];
                mma16816(accs[nt], ah, bl2);
                mma16816(accs[nt], al, bh2);
                mma16816(accs[nt], ah, bh2);
            }
        }

        // mask + tile max
        float tm0 = -3.0e38f, tm1 = -3.0e38f;
#pragma unroll
        for (int nt = 0; nt < 16; nt++) {
            int col = kt * 128 + nt * 8 + c2;
            int2 q0 = *reinterpret_cast<const int2*>(mrow0 + col);
            int2 q1 = *reinterpret_cast<const int2*>(mrow1 + col);
            if (q0.x == 0) accs[nt][0] = -1e9f;
            if (q0.y == 0) accs[nt][1] = -1e9f;
            if (q1.x == 0) accs[nt][2] = -1e9f;
            if (q1.y == 0) accs[nt][3] = -1e9f;
            tm0 = fmaxf(tm0, fmaxf(accs[nt][0], accs[nt][1]));
            tm1 = fmaxf(tm1, fmaxf(accs[nt][2], accs[nt][3]));
        }
        tm0 = fmaxf(tm0, __shfl_xor_sync(0xffffffffu, tm0, 1));
        tm0 = fmaxf(tm0, __shfl_xor_sync(0xffffffffu, tm0, 2));
        tm1 = fmaxf(tm1, __shfl_xor_sync(0xffffffffu, tm1, 1));
        tm1 = fmaxf(tm1, __shfl_xor_sync(0xffffffffu, tm1, 2));
        float M0 = fmaxf(m0, tm0), M1 = fmaxf(m1, tm1);
        float al0 = __expf(m0 - M0), al1 = __expf(m1 - M1);
        m0 = M0; m1 = M1;

        float s0 = 0.f, s1 = 0.f;
#pragma unroll
        for (int nt = 0; nt < 16; nt++) {
            accs[nt][0] = __expf(accs[nt][0] - M0);
            accs[nt][1] = __expf(accs[nt][1] - M0);
            accs[nt][2] = __expf(accs[nt][2] - M1);
            accs[nt][3] = __expf(accs[nt][3] - M1);
            s0 += accs[nt][0] + accs[nt][1];
            s1 += accs[nt][2] + accs[nt][3];
        }
        s0 += __shfl_xor_sync(0xffffffffu, s0, 1); s0 += __shfl_xor_sync(0xffffffffu, s0, 2);
        s1 += __shfl_xor_sync(0xffffffffu, s1, 1); s1 += __shfl_xor_sync(0xffffffffu, s1, 2);
        l0s = l0s * al0 + s0;
        l1s = l1s * al1 + s1;
#pragma unroll
        for (int nt = 0; nt < 8; nt++) {
            accc[nt][0] *= al0; accc[nt][1] *= al0;
            accc[nt][2] *= al1; accc[nt][3] *= al1;
        }
        // PV: P fragments built straight from accs (no smem round-trip)
#pragma unroll
        for (int t = 0; t < 8; t++) {
            unsigned a[4];
            a[0] = pack_bf2(accs[2 * t][0],     accs[2 * t][1]);
            a[1] = pack_bf2(accs[2 * t][2],     accs[2 * t][3]);
            a[2] = pack_bf2(accs[2 * t + 1][0], accs[2 * t + 1][1]);
            a[3] = pack_bf2(accs[2 * t + 1][2], accs[2 * t + 1][3]);
#pragma unroll
            for (int nt = 0; nt < 8; nt++) {
                int n = nt * 8 + (lane >> 2);
                unsigned bb[2];
                bb[0] = Vs[(8 * t + (lane & 3)) * VW + n];
                bb[1] = Vs[(8 * t + (lane & 3) + 4) * VW + n];
                mma16816(accc[nt], a, bb);
            }
        }
    }

    // epilogue: ctx in merged-head layout [B*S, D]
    float inv0 = 1.f / l0s, inv1 = 1.f / l1s;
    int row0 = qt * 128 + warp * 16 + (lane >> 2);
    float* Co = ctx + ((size_t)b * S_ + row0) * D_ + h * 64;
#pragma unroll
    for (int nt = 0; nt < 8; nt++) {
        int n = nt * 8 + c2;
        *reinterpret_cast<float2*>(Co + n) =
            make_float2(accc[nt][0] * inv0, accc[nt][1] * inv0);
        *reinterpret_cast<float2*>(Co + 8 * (size_t)D_ + n) =
            make_float2(accc[nt][2] * inv1, accc[nt][3] * inv1);
    }
}

// ---------------- launch ------------------------------------------------------
extern "C" void kernel_launch(void* const* d_in, const int* in_sizes, int n_in,
                              void* d_out, int out_size) {
    (void)in_sizes; (void)n_in; (void)out_size;
    const float* x   = (const float*)d_in[0];
    const int*   msk = (const int*)d_in[1];
    const float* Wq  = (const float*)d_in[2];
    const float* Wk  = (const float*)d_in[3];
    const float* Wv  = (const float*)d_in[4];
    const float* Wo  = (const float*)d_in[5];
    const float* bo  = (const float*)d_in[6];
    const float* g1  = (const float*)d_in[7];
    const float* be1 = (const float*)d_in[8];
    const float* g2  = (const float*)d_in[9];
    const float* be2 = (const float*)d_in[10];
    const float* W1  = (const float*)d_in[11];
    const float* b1  = (const float*)d_in[12];
    const float* W2  = (const float*)d_in[13];
    const float* b2  = (const float*)d_in[14];
    float* out = (float*)d_out;

    float *xa, *q, *k, *v, *ctx, *x2, *xf, *hid;
    cudaGetSymbolAddress((void**)&xa,  g_xa);
    cudaGetSymbolAddress((void**)&q,   g_q);
    cudaGetSymbolAddress((void**)&k,   g_k);
    cudaGetSymbolAddress((void**)&v,   g_v);
    cudaGetSymbolAddress((void**)&ctx, g_ctx);
    cudaGetSymbolAddress((void**)&x2,  g_x2);
    cudaGetSymbolAddress((void**)&xf,  g_xf);
    cudaGetSymbolAddress((void**)&hid, g_hid);

    constexpr int GEMM_SMEM  = 2 * (2 * 128 * 20 + 2 * 16 * 136) * 4;   // 75776 B
    constexpr int FLASH_SMEM = (4 * 128 * 36 + 64 * 72) * 4;            // 92160 B
    cudaFuncSetAttribute(gemm_mma<1>, cudaFuncAttributeMaxDynamicSharedMemorySize, GEMM_SMEM);
    cudaFuncSetAttribute(gemm_mma<2>, cudaFuncAttributeMaxDynamicSharedMemorySize, GEMM_SMEM);
    cudaFuncSetAttribute(gemm_mma<3>, cudaFuncAttributeMaxDynamicSharedMemorySize, GEMM_SMEM);
    cudaFuncSetAttribute(flash_kernel, cudaFuncAttributeMaxDynamicSharedMemorySize, FLASH_SMEM);

    // 1) LN1
    ln_kernel<<<BS_, 256>>>(x, g1, be1, xa);

    // 2) Q,K,V projections with split-heads epilogue
    dim3 gProj(D_ / 128, BS_ / 128, 1);
    gemm_mma<1><<<gProj, 256, GEMM_SMEM>>>(xa, Wq, q, D_, D_, D_, 0, nullptr, nullptr, 0);
    gemm_mma<1><<<gProj, 256, GEMM_SMEM>>>(xa, Wk, k, D_, D_, D_, 0, nullptr, nullptr, 0);
    gemm_mma<1><<<gProj, 256, GEMM_SMEM>>>(xa, Wv, v, D_, D_, D_, 0, nullptr, nullptr, 0);

    // 3) fused attention (QK^T + mask + softmax + PV)
    dim3 gFlash(1, S_ / 128, BH_);
    flash_kernel<<<gFlash, 256, FLASH_SMEM>>>(q, k, v, msk, ctx);

    // 4) x2 = x + ctx @ Wo + bo
    gemm_mma<2><<<gProj, 256, GEMM_SMEM>>>(ctx, Wo, x2, D_, D_, D_, D_, bo, x, D_);

    // 5) LN2
    ln_kernel<<<BS_, 256>>>(x2, g2, be2, xf);

    // 6) hid = relu(xf @ W1 + b1)
    dim3 gF1(DF_ / 128, BS_ / 128, 1);
    gemm_mma<3><<<gF1, 256, GEMM_SMEM>>>(xf, W1, hid, D_, D_, DF_, DF_, b1, nullptr, 0);

    // 7) out = x2 + hid @ W2 + b2
    dim3 gF2(D_ / 128, BS_ / 128, 1);
    gemm_mma<2><<<gF2, 256, GEMM_SMEM>>>(hid, W2, out, DF_, DF_, D_, D_, b2, x2, D_);
}

// round 4
// speedup vs baseline: 3.2772x; 1.0129x over previous
#include <cuda_runtime.h>
#include <cuda_bf16.h>
#include <math.h>

constexpr int B_  = 2;
constexpr int S_  = 2048;
constexpr int D_  = 1024;
constexpr int H_  = 16;
constexpr int DK_ = 64;
constexpr int DF_ = 4096;
constexpr int BS_ = B_ * S_;
constexpr int BH_ = B_ * H_;

// ---------------- scratch (static device globals; no allocs) ----------------
__device__ float g_xa[BS_ * D_];
__device__ float g_q[BH_ * S_ * DK_];
__device__ float g_k[BH_ * S_ * DK_];
__device__ float g_v[BH_ * S_ * DK_];
__device__ float g_ctx[BS_ * D_];
__device__ float g_x2[BS_ * D_];
__device__ float g_xf[BS_ * D_];
__device__ float g_hid[(long)BS_ * DF_];

// ---------------- helpers ----------------------------------------------------
__device__ __forceinline__ void split2(float x, float& hf, float& lf) {
    unsigned u = __float_as_uint(x) & 0xffff0000u;
    hf = __uint_as_float(u);
    lf = x - hf;
}
__device__ __forceinline__ unsigned pack_bf2(float lo, float hi) {
    unsigned r;
    asm("cvt.rn.bf16x2.f32 %0, %1, %2;" : "=r"(r) : "f"(hi), "f"(lo));
    return r;
}
__device__ __forceinline__ void mma16816(float* c, const unsigned* a, const unsigned* b) {
    asm volatile(
        "mma.sync.aligned.m16n8k16.row.col.f32.bf16.bf16.f32 "
        "{%0,%1,%2,%3},{%4,%5,%6,%7},{%8,%9},{%0,%1,%2,%3};\n"
        : "+f"(c[0]), "+f"(c[1]), "+f"(c[2]), "+f"(c[3])
        : "r"(a[0]), "r"(a[1]), "r"(a[2]), "r"(a[3]), "r"(b[0]), "r"(b[1]));
}
__device__ __forceinline__ void ldsm_x4(unsigned& r0, unsigned& r1, unsigned& r2, unsigned& r3,
                                        unsigned addr) {
    asm volatile("ldmatrix.sync.aligned.m8n8.x4.shared.b16 {%0,%1,%2,%3}, [%4];"
                 : "=r"(r0), "=r"(r1), "=r"(r2), "=r"(r3) : "r"(addr));
}
__device__ __forceinline__ void ldsm_x4t(unsigned& r0, unsigned& r1, unsigned& r2, unsigned& r3,
                                         unsigned addr) {
    asm volatile("ldmatrix.sync.aligned.m8n8.x4.trans.shared.b16 {%0,%1,%2,%3}, [%4];"
                 : "=r"(r0), "=r"(r1), "=r"(r2), "=r"(r3) : "r"(addr));
}

// ---------------- LayerNorm ---------------------------------------------------
__global__ void ln_kernel(const float* __restrict__ x, const float* __restrict__ g,
                          const float* __restrict__ b, float* __restrict__ out) {
    constexpr int NCOL = D_ / 256;
    int row = blockIdx.x;
    const float* xr = x + (size_t)row * D_;
    float v[NCOL];
    float s = 0.f, s2 = 0.f;
#pragma unroll
    for (int i = 0; i < NCOL; i++) {
        float t = xr[threadIdx.x + i * 256];
        v[i] = t; s += t; s2 += t * t;
    }
#pragma unroll
    for (int o = 16; o > 0; o >>= 1) {
        s  += __shfl_xor_sync(0xffffffffu, s, o);
        s2 += __shfl_xor_sync(0xffffffffu, s2, o);
    }
    __shared__ float sh[2][8];
    int warp = threadIdx.x >> 5, lane = threadIdx.x & 31;
    if (lane == 0) { sh[0][warp] = s; sh[1][warp] = s2; }
    __syncthreads();
    if (warp == 0) {
        s  = (lane < 8) ? sh[0][lane] : 0.f;
        s2 = (lane < 8) ? sh[1][lane] : 0.f;
#pragma unroll
        for (int o = 4; o > 0; o >>= 1) {
            s  += __shfl_xor_sync(0xffffffffu, s, o);
            s2 += __shfl_xor_sync(0xffffffffu, s2, o);
        }
        if (lane == 0) { sh[0][0] = s; sh[1][0] = s2; }
    }
    __syncthreads();
    float mu  = sh[0][0] * (1.f / D_);
    float var = sh[1][0] * (1.f / D_) - mu * mu;
    float rstd = rsqrtf(var + 1e-5f);
    float* orow = out + (size_t)row * D_;
#pragma unroll
    for (int i = 0; i < NCOL; i++) {
        int c = threadIdx.x + i * 256;
        orow[c] = (v[i] - mu) * rstd * g[c] + b[c];
    }
}

// ---------------- pipelined bf16-split tensor-core GEMM (ldmatrix) -----------
// C = A(MxK fp32) * B(KxN fp32) [+bias][+relu][+residual]
// A smem: u32 k-pair words [row][20], hi+lo planes. (pitch 20 w: stride%32=20.. used via ldmatrix)
// B smem: bf16 [k][136] row-major, hi+lo planes (pitch 68 w, stride%32=4 -> conflict-free LDSM).
// EPI: 1 split-heads, 2 bias+residual, 3 bias+relu
template<int EPI>
__global__ void __launch_bounds__(256, 1)
gemm_mma(const float* __restrict__ A, const float* __restrict__ Bp, float* __restrict__ C,
         int K, int lda, int ldb, int ldc,
         const float* __restrict__ bias, const float* __restrict__ res, int ldres) {
    constexpr int BM = 128, BN = 128, BK = 32;
    constexpr int KWA = 20;                 // A pitch (u32 words)
    constexpr int BP  = 68;                 // B pitch (u32 words) = 136 bf16
    constexpr int APL = BM * KWA;           // 2560 words per A plane
    constexpr int BPL = BK * BP;            // 2176 words per B plane
    constexpr int AW  = 2 * APL;            // 5120
    constexpr int BW  = 2 * BPL;            // 4352
    constexpr int SS  = AW + BW;            // 9472 words per stage
    extern __shared__ unsigned sm[];
    const unsigned smb = (unsigned)__cvta_generic_to_shared(sm);

    const int tid = threadIdx.x, warp = tid >> 5, lane = tid & 31;
    const int wm = warp >> 2, wn = warp & 3;
    const int bm = blockIdx.y * BM, bn = blockIdx.x * BN;
    constexpr int MT = 4, NT = 4;

    float acc[MT][NT][4] = {};
    float4 ra[4], rb0[2], rb1[2];
    const int arow = tid >> 3, aq = tid & 7;

    auto loadAB = [&](int k0) {
#pragma unroll
        for (int i = 0; i < 4; i++)
            ra[i] = *reinterpret_cast<const float4*>(
                A + (size_t)(bm + arow + i * 32) * lda + k0 + aq * 4);
#pragma unroll
        for (int i = 0; i < 2; i++) {
            int kp = warp + i * 8;
            const float* p0 = Bp + (size_t)(k0 + 2 * kp) * ldb + bn + lane * 4;
            rb0[i] = *reinterpret_cast<const float4*>(p0);
            rb1[i] = *reinterpret_cast<const float4*>(p0 + ldb);
        }
    };
    auto stage_store = [&](int st) {
        unsigned* base = sm + st * SS;
#pragma unroll
        for (int i = 0; i < 4; i++) {
            int row = arow + i * 32;
            float h0, l0, h1, l1, h2, l2, h3, l3;
            split2(ra[i].x, h0, l0); split2(ra[i].y, h1, l1);
            split2(ra[i].z, h2, l2); split2(ra[i].w, h3, l3);
            *reinterpret_cast<uint2*>(base + row * KWA + aq * 2) =
                make_uint2(pack_bf2(h0, h1), pack_bf2(h2, h3));
            *reinterpret_cast<uint2*>(base + APL + row * KWA + aq * 2) =
                make_uint2(pack_bf2(l0, l1), pack_bf2(l2, l3));
        }
        unsigned* bb = base + AW;
#pragma unroll
        for (int i = 0; i < 2; i++) {
            int kp = warp + i * 8;
            float h0, l0, h1, l1, h2, l2, h3, l3;
            // row k=2kp from rb0
            split2(rb0[i].x, h0, l0); split2(rb0[i].y, h1, l1);
            split2(rb0[i].z, h2, l2); split2(rb0[i].w, h3, l3);
            *reinterpret_cast<uint2*>(bb + (2 * kp) * BP + lane * 2) =
                make_uint2(pack_bf2(h0, h1), pack_bf2(h2, h3));
            *reinterpret_cast<uint2*>(bb + BPL + (2 * kp) * BP + lane * 2) =
                make_uint2(pack_bf2(l0, l1), pack_bf2(l2, l3));
            // row k=2kp+1 from rb1
            split2(rb1[i].x, h0, l0); split2(rb1[i].y, h1, l1);
            split2(rb1[i].z, h2, l2); split2(rb1[i].w, h3, l3);
            *reinterpret_cast<uint2*>(bb + (2 * kp + 1) * BP + lane * 2) =
                make_uint2(pack_bf2(h0, h1), pack_bf2(h2, h3));
            *reinterpret_cast<uint2*>(bb + BPL + (2 * kp + 1) * BP + lane * 2) =
                make_uint2(pack_bf2(l0, l1), pack_bf2(l2, l3));
        }
    };
    auto do_mma = [&](int st) {
        const unsigned stb = smb + st * SS * 4;
#pragma unroll
        for (int s = 0; s < 2; s++) {
            // A fragment addresses (ldmatrix x4, non-trans)
            int ar = wm * 64 + (lane & 7) + ((lane >> 3) & 1) * 8;
            int ak = s * 8 + (lane >> 4) * 4;
            unsigned afh[MT][4], afl[MT][4];
#pragma unroll
            for (int mt = 0; mt < MT; mt++) {
                unsigned ad = stb + (unsigned)(((ar + mt * 16) * KWA + ak) * 4);
                ldsm_x4(afh[mt][0], afh[mt][1], afh[mt][2], afh[mt][3], ad);
                ldsm_x4(afl[mt][0], afl[mt][1], afl[mt][2], afl[mt][3], ad + APL * 4);
            }
            // B fragment addresses (ldmatrix x4 trans): bf16 [k][136]
            int bk = s * 16 + (lane & 7) + ((lane >> 3) & 1) * 8;
            unsigned bfh[NT][2], bfl[NT][2];
#pragma unroll
            for (int j = 0; j < 2; j++) {
                int n = wn * 32 + j * 16 + (lane >> 4) * 8;
                unsigned ad = stb + AW * 4 + (unsigned)(bk * 272 + n * 2);
                ldsm_x4t(bfh[2 * j][0], bfh[2 * j][1], bfh[2 * j + 1][0], bfh[2 * j + 1][1], ad);
                ldsm_x4t(bfl[2 * j][0], bfl[2 * j][1], bfl[2 * j + 1][0], bfl[2 * j + 1][1],
                         ad + BPL * 4);
            }
#pragma unroll
            for (int mt = 0; mt < MT; mt++)
#pragma unroll
                for (int nt = 0; nt < NT; nt++) {
                    mma16816(acc[mt][nt], afh[mt], bfl[nt]);
                    mma16816(acc[mt][nt], afl[mt], bfh[nt]);
                    mma16816(acc[mt][nt], afh[mt], bfh[nt]);
                }
        }
    };

    const int nk = K / BK;
    loadAB(0);
    stage_store(0);
    __syncthreads();
    for (int i = 0; i < nk; i++) {
        if (i + 1 < nk) loadAB((i + 1) * BK);
        do_mma(i & 1);
        if (i + 1 < nk) stage_store((i + 1) & 1);
        __syncthreads();
    }

#pragma unroll
    for (int mt = 0; mt < MT; mt++) {
#pragma unroll
        for (int half = 0; half < 2; half++) {
            int m = bm + wm * 64 + mt * 16 + (lane >> 2) + half * 8;
#pragma unroll
            for (int nt = 0; nt < NT; nt++) {
                int n = bn + wn * 32 + nt * 8 + (lane & 3) * 2;
                float v0 = acc[mt][nt][half * 2 + 0];
                float v1 = acc[mt][nt][half * 2 + 1];
                if (EPI == 1) {
                    int bh = (m >> 11) * H_ + (n >> 6);
                    size_t base = ((size_t)bh * S_ + (m & (S_ - 1))) * DK_ + (n & (DK_ - 1));
                    C[base]     = v0;
                    C[base + 1] = v1;
                } else if (EPI == 2) {
                    C[(size_t)m * ldc + n]     = v0 + bias[n]     + res[(size_t)m * ldres + n];
                    C[(size_t)m * ldc + n + 1] = v1 + bias[n + 1] + res[(size_t)m * ldres + n + 1];
                } else {
                    C[(size_t)m * ldc + n]     = fmaxf(v0 + bias[n], 0.f);
                    C[(size_t)m * ldc + n + 1] = fmaxf(v1 + bias[n + 1], 0.f);
                }
            }
        }
    }
}

// ---------------- fused flash attention (ldmatrix) ---------------------------
// grid (1, S/128, B*H); block 256 (8 warps x 16 q-rows each).
// Q,K: u32 kpair words [row][36], hi+lo planes (LDSM non-trans).
// V:   bf16 [key][72] row-major (LDSM trans).
constexpr int QW = 36;                       // Q/K pitch (u32 words)
constexpr int QPL = 128 * QW;                // plane words
constexpr int VP  = 36;                      // V pitch in u32 words (72 bf16)
__global__ void __launch_bounds__(256, 1)
flash_kernel(const float* __restrict__ q, const float* __restrict__ k,
             const float* __restrict__ v, const int* __restrict__ mask,
             float* __restrict__ ctx) {
    extern __shared__ unsigned sm[];
    const unsigned smb = (unsigned)__cvta_generic_to_shared(sm);
    unsigned* Qs = sm;                       // hi plane, lo at +QPL
    unsigned* Ks = sm + 2 * QPL;
    unsigned* Vs = sm + 4 * QPL;             // [128][36]
    const unsigned qb = smb;
    const unsigned kb = smb + 2 * QPL * 4;
    const unsigned vb = smb + 4 * QPL * 4;
    const int tid = threadIdx.x, warp = tid >> 5, lane = tid & 31;
    const int bh = blockIdx.z, qt = blockIdx.y;
    const int b = bh >> 4, h = bh & 15;
    const float* Qp = q + ((size_t)bh * S_ + qt * 128) * DK_;
    const float* Kp = k + (size_t)bh * S_ * DK_;
    const float* Vp = v + (size_t)bh * S_ * DK_;
    const int*   Mp = mask + ((size_t)b * S_ + qt * 128) * (size_t)S_;

    // Q tile (pre-scaled by 1/8), split hi/lo
#pragma unroll
    for (int i = 0; i < 8; i++) {
        int idx = tid + i * 256;
        int row = idx >> 4, q4 = idx & 15;
        float4 a = *reinterpret_cast<const float4*>(Qp + row * 64 + q4 * 4);
        a.x *= 0.125f; a.y *= 0.125f; a.z *= 0.125f; a.w *= 0.125f;
        float h0, l0, h1, l1, h2, l2, h3, l3;
        split2(a.x, h0, l0); split2(a.y, h1, l1);
        split2(a.z, h2, l2); split2(a.w, h3, l3);
        *reinterpret_cast<uint2*>(Qs + row * QW + q4 * 2) =
            make_uint2(pack_bf2(h0, h1), pack_bf2(h2, h3));
        *reinterpret_cast<uint2*>(Qs + QPL + row * QW + q4 * 2) =
            make_uint2(pack_bf2(l0, l1), pack_bf2(l2, l3));
    }

    float accc[8][4] = {};
    float m0 = -3.0e38f, m1 = -3.0e38f, l0s = 0.f, l1s = 0.f;
    const int c2 = (lane & 3) * 2;
    const int* mrow0 = Mp + ((size_t)(warp * 16 + (lane >> 2))) * S_;
    const int* mrow1 = mrow0 + 8 * (size_t)S_;

    for (int kt = 0; kt < S_ / 128; kt++) {
        __syncthreads();
        // K tile: split hi/lo
#pragma unroll
        for (int i = 0; i < 8; i++) {
            int idx = tid + i * 256;
            int row = idx >> 4, q4 = idx & 15;
            float4 a = *reinterpret_cast<const float4*>(
                Kp + (size_t)(kt * 128 + row) * 64 + q4 * 4);
            float h0, l0, h1, l1, h2, l2, h3, l3;
            split2(a.x, h0, l0); split2(a.y, h1, l1);
            split2(a.z, h2, l2); split2(a.w, h3, l3);
            *reinterpret_cast<uint2*>(Ks + row * QW + q4 * 2) =
                make_uint2(pack_bf2(h0, h1), pack_bf2(h2, h3));
            *reinterpret_cast<uint2*>(Ks + QPL + row * QW + q4 * 2) =
                make_uint2(pack_bf2(l0, l1), pack_bf2(l2, l3));
        }
        // V tile: plain bf16 [key][72]
#pragma unroll
        for (int i = 0; i < 8; i++) {
            int idx = tid + i * 256;
            int row = idx >> 4, dk4 = idx & 15;
            float4 a = *reinterpret_cast<const float4*>(
                Vp + (size_t)(kt * 128 + row) * 64 + dk4 * 4);
            *reinterpret_cast<uint2*>(Vs + row * VP + dk4 * 2) =
                make_uint2(pack_bf2(a.x, a.y), pack_bf2(a.z, a.w));
        }
        __syncthreads();

        // S = Q K^T : accs[16][4]
        float accs[16][4] = {};
#pragma unroll
        for (int s = 0; s < 4; s++) {
            int qr = warp * 16 + (lane & 7) + ((lane >> 3) & 1) * 8;
            int qk = s * 8 + (lane >> 4) * 4;
            unsigned ah[4], al[4];
            unsigned qad = qb + (unsigned)((qr * QW + qk) * 4);
            ldsm_x4(ah[0], ah[1], ah[2], ah[3], qad);
            ldsm_x4(al[0], al[1], al[2], al[3], qad + QPL * 4);
            int krB = (lane & 7) + (lane >> 4) * 8;
            int kkp = s * 8 + ((lane >> 3) & 1) * 4;
#pragma unroll
            for (int j = 0; j < 8; j++) {
                unsigned kad = kb + (unsigned)(((j * 16 + krB) * QW + kkp) * 4);
                unsigned bh2[2], bh3[2], bl2[2], bl3[2];
                ldsm_x4(bh2[0], bh2[1], bh3[0], bh3[1], kad);
                ldsm_x4(bl2[0], bl2[1], bl3[0], bl3[1], kad + QPL * 4);
                mma16816(accs[2 * j], ah, bl2);
                mma16816(accs[2 * j], al, bh2);
                mma16816(accs[2 * j], ah, bh2);
                mma16816(accs[2 * j + 1], ah, bl3);
                mma16816(accs[2 * j + 1], al, bh3);
                mma16816(accs[2 * j + 1], ah, bh3);
            }
        }

        // mask + tile max
        float tm0 = -3.0e38f, tm1 = -3.0e38f;
#pragma unroll
        for (int nt = 0; nt < 16; nt++) {
            int col = kt * 128 + nt * 8 + c2;
            int2 q0 = *reinterpret_cast<const int2*>(mrow0 + col);
            int2 q1 = *reinterpret_cast<const int2*>(mrow1 + col);
            if (q0.x == 0) accs[nt][0] = -1e9f;
            if (q0.y == 0) accs[nt][1] = -1e9f;
            if (q1.x == 0) accs[nt][2] = -1e9f;
            if (q1.y == 0) accs[nt][3] = -1e9f;
            tm0 = fmaxf(tm0, fmaxf(accs[nt][0], accs[nt][1]));
            tm1 = fmaxf(tm1, fmaxf(accs[nt][2], accs[nt][3]));
        }
        tm0 = fmaxf(tm0, __shfl_xor_sync(0xffffffffu, tm0, 1));
        tm0 = fmaxf(tm0, __shfl_xor_sync(0xffffffffu, tm0, 2));
        tm1 = fmaxf(tm1, __shfl_xor_sync(0xffffffffu, tm1, 1));
        tm1 = fmaxf(tm1, __shfl_xor_sync(0xffffffffu, tm1, 2));
        float M0 = fmaxf(m0, tm0), M1 = fmaxf(m1, tm1);
        float al0 = __expf(m0 - M0), al1 = __expf(m1 - M1);
        m0 = M0; m1 = M1;

        float s0 = 0.f, s1 = 0.f;
#pragma unroll
        for (int nt = 0; nt < 16; nt++) {
            accs[nt][0] = __expf(accs[nt][0] - M0);
            accs[nt][1] = __expf(accs[nt][1] - M0);
            accs[nt][2] = __expf(accs[nt][2] - M1);
            accs[nt][3] = __expf(accs[nt][3] - M1);
            s0 += accs[nt][0] + accs[nt][1];
            s1 += accs[nt][2] + accs[nt][3];
        }
        s0 += __shfl_xor_sync(0xffffffffu, s0, 1); s0 += __shfl_xor_sync(0xffffffffu, s0, 2);
        s1 += __shfl_xor_sync(0xffffffffu, s1, 1); s1 += __shfl_xor_sync(0xffffffffu, s1, 2);
        l0s = l0s * al0 + s0;
        l1s = l1s * al1 + s1;
#pragma unroll
        for (int nt = 0; nt < 8; nt++) {
            accc[nt][0] *= al0; accc[nt][1] *= al0;
            accc[nt][2] *= al1; accc[nt][3] *= al1;
        }
        // PV: P fragments from accs; V frags via ldmatrix trans
        int vkB = (lane & 7) + ((lane >> 3) & 1) * 8;
        int vnB = (lane >> 4) * 8;
#pragma unroll
        for (int t = 0; t < 8; t++) {
            unsigned a[4];
            a[0] = pack_bf2(accs[2 * t][0],     accs[2 * t][1]);
            a[1] = pack_bf2(accs[2 * t][2],     accs[2 * t][3]);
            a[2] = pack_bf2(accs[2 * t + 1][0], accs[2 * t + 1][1]);
            a[3] = pack_bf2(accs[2 * t + 1][2], accs[2 * t + 1][3]);
            int vk = 16 * t + vkB;
#pragma unroll
            for (int j = 0; j < 4; j++) {
                int n = j * 16 + vnB;
                unsigned vad = vb + (unsigned)(vk * 144 + n * 2);  // pitch 72 bf16 = 144 B
                unsigned b0[2], b1[2];
                ldsm_x4t(b0[0], b0[1], b1[0], b1[1], vad);
                mma16816(accc[2 * j],     a, b0);
                mma16816(accc[2 * j + 1], a, b1);
            }
        }
    }

    // epilogue: ctx in merged-head layout [B*S, D]
    float inv0 = 1.f / l0s, inv1 = 1.f / l1s;
    int row0 = qt * 128 + warp * 16 + (lane >> 2);
    float* Co = ctx + ((size_t)b * S_ + row0) * D_ + h * 64;
#pragma unroll
    for (int nt = 0; nt < 8; nt++) {
        int n = nt * 8 + c2;
        *reinterpret_cast<float2*>(Co + n) =
            make_float2(accc[nt][0] * inv0, accc[nt][1] * inv0);
        *reinterpret_cast<float2*>(Co + 8 * (size_t)D_ + n) =
            make_float2(accc[nt][2] * inv1, accc[nt][3] * inv1);
    }
}

// ---------------- launch ------------------------------------------------------
extern "C" void kernel_launch(void* const* d_in, const int* in_sizes, int n_in,
                              void* d_out, int out_size) {
    (void)in_sizes; (void)n_in; (void)out_size;
    const float* x   = (const float*)d_in[0];
    const int*   msk = (const int*)d_in[1];
    const float* Wq  = (const float*)d_in[2];
    const float* Wk  = (const float*)d_in[3];
    const float* Wv  = (const float*)d_in[4];
    const float* Wo  = (const float*)d_in[5];
    const float* bo  = (const float*)d_in[6];
    const float* g1  = (const float*)d_in[7];
    const float* be1 = (const float*)d_in[8];
    const float* g2  = (const float*)d_in[9];
    const float* be2 = (const float*)d_in[10];
    const float* W1  = (const float*)d_in[11];
    const float* b1  = (const float*)d_in[12];
    const float* W2  = (const float*)d_in[13];
    const float* b2  = (const float*)d_in[14];
    float* out = (float*)d_out;

    float *xa, *q, *k, *v, *ctx, *x2, *xf, *hid;
    cudaGetSymbolAddress((void**)&xa,  g_xa);
    cudaGetSymbolAddress((void**)&q,   g_q);
    cudaGetSymbolAddress((void**)&k,   g_k);
    cudaGetSymbolAddress((void**)&v,   g_v);
    cudaGetSymbolAddress((void**)&ctx, g_ctx);
    cudaGetSymbolAddress((void**)&x2,  g_x2);
    cudaGetSymbolAddress((void**)&xf,  g_xf);
    cudaGetSymbolAddress((void**)&hid, g_hid);

    constexpr int GEMM_SMEM  = 2 * (2 * 128 * 20 + 2 * 32 * 68) * 4;    // 75776 B
    constexpr int FLASH_SMEM = (4 * 128 * 36 + 128 * 36) * 4;           // 92160 B
    cudaFuncSetAttribute(gemm_mma<1>, cudaFuncAttributeMaxDynamicSharedMemorySize, GEMM_SMEM);
    cudaFuncSetAttribute(gemm_mma<2>, cudaFuncAttributeMaxDynamicSharedMemorySize, GEMM_SMEM);
    cudaFuncSetAttribute(gemm_mma<3>, cudaFuncAttributeMaxDynamicSharedMemorySize, GEMM_SMEM);
    cudaFuncSetAttribute(flash_kernel, cudaFuncAttributeMaxDynamicSharedMemorySize, FLASH_SMEM);

    // 1) LN1
    ln_kernel<<<BS_, 256>>>(x, g1, be1, xa);

    // 2) Q,K,V projections with split-heads epilogue
    dim3 gProj(D_ / 128, BS_ / 128, 1);
    gemm_mma<1><<<gProj, 256, GEMM_SMEM>>>(xa, Wq, q, D_, D_, D_, 0, nullptr, nullptr, 0);
    gemm_mma<1><<<gProj, 256, GEMM_SMEM>>>(xa, Wk, k, D_, D_, D_, 0, nullptr, nullptr, 0);
    gemm_mma<1><<<gProj, 256, GEMM_SMEM>>>(xa, Wv, v, D_, D_, D_, 0, nullptr, nullptr, 0);

    // 3) fused attention (QK^T + mask + softmax + PV)
    dim3 gFlash(1, S_ / 128, BH_);
    flash_kernel<<<gFlash, 256, FLASH_SMEM>>>(q, k, v, msk, ctx);

    // 4) x2 = x + ctx @ Wo + bo
    gemm_mma<2><<<gProj, 256, GEMM_SMEM>>>(ctx, Wo, x2, D_, D_, D_, D_, bo, x, D_);

    // 5) LN2
    ln_kernel<<<BS_, 256>>>(x2, g2, be2, xf);

    // 6) hid = relu(xf @ W1 + b1)
    dim3 gF1(DF_ / 128, BS_ / 128, 1);
    gemm_mma<3><<<gF1, 256, GEMM_SMEM>>>(xf, W1, hid, D_, D_, DF_, DF_, b1, nullptr, 0);

    // 7) out = x2 + hid @ W2 + b2
    dim3 gF2(D_ / 128, BS_ / 128, 1);
    gemm_mma<2><<<gF2, 256, GEMM_SMEM>>>(hid, W2, out, DF_, DF_, D_, D_, b2, x2, D_);
}